// round 3
// baseline (speedup 1.0000x reference)
#include <cuda_runtime.h>
#include <cuda_bf16.h>

// GDLoss: elementwise Gaussian KL-distance loss over [N,5] xywhr boxes.
// R3: R1 geometry (256 thr, 1 box/thread, 10KB smem, occ ~91%) but staging
// via LDG.128 (320 float4 per tensor per block, <=2 per thread) to cut the
// issue-side instruction count that co-limited R1.

#define TAU_F   1.0f
#define EPS_F   1e-6f
#define BLK     256
#define NF      (BLK * 5)        // 1280 floats per tensor per block
#define NV4     (NF / 4)         // 320 float4 per tensor per block

__device__ __forceinline__ float gd_loss_one(
    float px, float py, float pw, float ph, float prr,
    float tx, float ty, float tw, float th, float trr)
{
    pw = fminf(fmaxf(pw, 1e-7f), 1e7f);
    ph = fminf(fmaxf(ph, 1e-7f), 1e7f);
    tw = fminf(fmaxf(tw, 1e-7f), 1e7f);
    th = fminf(fmaxf(th, 1e-7f), 1e7f);

    float cp, spn, ct, stn;
    __sincosf(prr, &spn, &cp);
    __sincosf(trr, &stn, &ct);

    const float pa = 0.25f * pw * pw;
    const float pb = 0.25f * ph * ph;
    const float p11 = pa * cp * cp + pb * spn * spn;
    const float p12 = (pa - pb) * spn * cp;
    const float p22 = pa * spn * spn + pb * cp * cp;

    const float ta = 0.25f * tw * tw;
    const float tb = 0.25f * th * th;
    const float t11 = ta * ct * ct + tb * stn * stn;
    const float t12 = (ta - tb) * stn * ct;
    const float t22 = ta * stn * stn + tb * ct * ct;

    const float det_p = p11 * p22 - p12 * p12;
    const float det_t = t11 * t22 - t12 * t12;

    const float dx = px - tx;
    const float dy = py - ty;

    const float inv_det_t = __frcp_rn(det_t);

    const float term1 = (t22 * dx * dx - 2.0f * t12 * dx * dy + t11 * dy * dy) * inv_det_t;
    const float trace_term = (t22 * p11 - 2.0f * t12 * p12 + t11 * p22) * inv_det_t;
    const float term2 = trace_term + __logf(det_t * __frcp_rn(det_p));

    float dis = term1 + term2 - 2.0f;
    float kl = fmaxf(dis, EPS_F);
    return 1.0f - __frcp_rn(TAU_F + sqrtf(kl));
}

__global__ void __launch_bounds__(BLK) gd_loss_kernel(
    const float* __restrict__ pred,
    const float* __restrict__ target,
    float* __restrict__ out,
    int n)
{
    __shared__ float sp[NF];
    __shared__ float st[NF];

    const int tid = threadIdx.x;
    const long long blockBase = (long long)blockIdx.x * BLK;
    int nb = n - (int)blockBase;
    if (nb <= 0) return;
    if (nb > BLK) nb = BLK;

    const float* __restrict__ pbase = pred   + blockBase * 5;
    const float* __restrict__ tbase = target + blockBase * 5;

    if (nb == BLK) {
        // Full block (all blocks when N % 256 == 0): vectorized staging.
        // 320 float4 per tensor; thread does 1 or 2 LDG.128 per tensor.
        const float4* __restrict__ p4 = (const float4*)pbase;
        const float4* __restrict__ t4 = (const float4*)tbase;
        float4* __restrict__ sp4 = (float4*)sp;
        float4* __restrict__ st4 = (float4*)st;
        #pragma unroll
        for (int j = 0; j < 2; ++j) {
            const int i = tid + j * BLK;
            if (i < NV4) {
                sp4[i] = p4[i];
                st4[i] = t4[i];
            }
        }
    } else {
        // Tail block (not hit for N=4M): scalar guarded staging.
        const int nfloats = nb * 5;
        for (int i = tid; i < nfloats; i += BLK) {
            sp[i] = pbase[i];
            st[i] = tbase[i];
        }
    }
    __syncthreads();

    if (tid < nb) {
        const int b5 = tid * 5;  // stride-5 smem: gcd(5,32)=1, conflict-free
        const float loss = gd_loss_one(
            sp[b5 + 0], sp[b5 + 1], sp[b5 + 2], sp[b5 + 3], sp[b5 + 4],
            st[b5 + 0], st[b5 + 1], st[b5 + 2], st[b5 + 3], st[b5 + 4]);
        out[blockBase + tid] = loss;
    }
}

extern "C" void kernel_launch(void* const* d_in, const int* in_sizes, int n_in,
                              void* d_out, int out_size)
{
    const float* pred   = (const float*)d_in[0];
    const float* target = (const float*)d_in[1];
    // d_in[2] (weight) is unused by the reference computation (LOSS_WEIGHT=1).
    float* out = (float*)d_out;

    const int n = out_size;  // N boxes; output is [N,1] floats
    const int grid = (n + BLK - 1) / BLK;
    gd_loss_kernel<<<grid, BLK>>>(pred, target, out, n);
}

// round 5
// speedup vs baseline: 1.2369x; 1.2369x over previous
#include <cuda_runtime.h>
#include <cuda_bf16.h>
#include <cstdint>

// GDLoss: elementwise Gaussian KL loss over [N,5] xywhr boxes. 176MB traffic.
// R5 (= R4 + compile fix): cp.async.cg double-buffered pipeline, 5 tiles x 256
// boxes per block. Fixes the load->sync->compute convoy that capped DRAM at
// ~55% in R1-R3: tile t+1's LDGSTS are in flight while tile t computes.

#define TAU_F   1.0f
#define EPS_F   1e-6f
#define BLK     256
#define TPB     5                    // tiles per block; 4M = 256*5*3125 exactly
#define TILE_F  (BLK * 5)            // 1280 floats per tensor per tile
#define TILE_V4 (TILE_F / 4)         // 320 float4 per tensor per tile

__device__ __forceinline__ void cp_async16(unsigned smem_dst, const void* gmem_src) {
    asm volatile("cp.async.cg.shared.global [%0], [%1], 16;\n"
                 :: "r"(smem_dst), "l"(gmem_src));
}
__device__ __forceinline__ void cp_async4(unsigned smem_dst, const void* gmem_src) {
    asm volatile("cp.async.ca.shared.global [%0], [%1], 4;\n"
                 :: "r"(smem_dst), "l"(gmem_src));
}
__device__ __forceinline__ void cp_commit() {
    asm volatile("cp.async.commit_group;\n" ::: "memory");
}
template <int N>
__device__ __forceinline__ void cp_wait() {
    asm volatile("cp.async.wait_group %0;\n" :: "n"(N) : "memory");
}

__device__ __forceinline__ float gd_loss_one(
    float px, float py, float pw, float ph, float prr,
    float tx, float ty, float tw, float th, float trr)
{
    pw = fminf(fmaxf(pw, 1e-7f), 1e7f);
    ph = fminf(fmaxf(ph, 1e-7f), 1e7f);
    tw = fminf(fmaxf(tw, 1e-7f), 1e7f);
    th = fminf(fmaxf(th, 1e-7f), 1e7f);

    float cp, spn, ct, stn;
    __sincosf(prr, &spn, &cp);
    __sincosf(trr, &stn, &ct);

    const float pa = 0.25f * pw * pw;
    const float pb = 0.25f * ph * ph;
    const float p11 = pa * cp * cp + pb * spn * spn;
    const float p12 = (pa - pb) * spn * cp;
    const float p22 = pa * spn * spn + pb * cp * cp;

    const float ta = 0.25f * tw * tw;
    const float tb = 0.25f * th * th;
    const float t11 = ta * ct * ct + tb * stn * stn;
    const float t12 = (ta - tb) * stn * ct;
    const float t22 = ta * stn * stn + tb * ct * ct;

    const float det_p = p11 * p22 - p12 * p12;
    const float det_t = t11 * t22 - t12 * t12;

    const float dx = px - tx;
    const float dy = py - ty;

    const float inv_det_t = __frcp_rn(det_t);

    const float term1 = (t22 * dx * dx - 2.0f * t12 * dx * dy + t11 * dy * dy) * inv_det_t;
    const float trace_term = (t22 * p11 - 2.0f * t12 * p12 + t11 * p22) * inv_det_t;
    const float term2 = trace_term + __logf(det_t * __frcp_rn(det_p));

    float dis = term1 + term2 - 2.0f;
    float kl = fmaxf(dis, EPS_F);
    return 1.0f - __frcp_rn(TAU_F + sqrtf(kl));
}

__global__ void __launch_bounds__(BLK) gd_loss_kernel(
    const float* __restrict__ pred,
    const float* __restrict__ target,
    float* __restrict__ out,
    int n)
{
    __shared__ float sp[2][TILE_F];
    __shared__ float st[2][TILE_F];

    const int tid = threadIdx.x;
    const long long blockBase = (long long)blockIdx.x * (BLK * TPB);

    // Issue staged loads for tile s into buffer (s & 1).
    auto issue_tile = [&](int s) {
        const long long tileBase = blockBase + (long long)s * BLK;
        long long nb = (long long)n - tileBase;
        if (nb <= 0) { cp_commit(); return; }
        if (nb > BLK) nb = BLK;
        float* spb = sp[s & 1];
        float* stb = st[s & 1];
        const float* pbase = pred   + tileBase * 5;
        const float* tbase = target + tileBase * 5;
        if (nb == BLK) {
            const float4* p4 = (const float4*)pbase;
            const float4* t4 = (const float4*)tbase;
            #pragma unroll
            for (int j = 0; j < 2; ++j) {
                const int i = tid + j * BLK;
                if (i < TILE_V4) {
                    cp_async16((unsigned)__cvta_generic_to_shared(((float4*)spb) + i), p4 + i);
                    cp_async16((unsigned)__cvta_generic_to_shared(((float4*)stb) + i), t4 + i);
                }
            }
        } else {
            const int nfloats = (int)nb * 5;
            for (int i = tid; i < nfloats; i += BLK) {
                cp_async4((unsigned)__cvta_generic_to_shared(spb + i), pbase + i);
                cp_async4((unsigned)__cvta_generic_to_shared(stb + i), tbase + i);
            }
        }
        cp_commit();
    };

    issue_tile(0);
    issue_tile(1);

    #pragma unroll
    for (int s = 0; s < TPB; ++s) {
        if (s + 1 < TPB) cp_wait<1>(); else cp_wait<0>();
        __syncthreads();

        const long long tileBase = blockBase + (long long)s * BLK;
        long long nbll = (long long)n - tileBase;
        const int nb = (nbll >= BLK) ? BLK : (nbll > 0 ? (int)nbll : 0);

        if (tid < nb) {
            const float* spb = sp[s & 1];
            const float* stb = st[s & 1];
            const int b5 = tid * 5;   // stride-5 smem: gcd(5,32)=1, conflict-free
            const float loss = gd_loss_one(
                spb[b5 + 0], spb[b5 + 1], spb[b5 + 2], spb[b5 + 3], spb[b5 + 4],
                stb[b5 + 0], stb[b5 + 1], stb[b5 + 2], stb[b5 + 3], stb[b5 + 4]);
            out[tileBase + tid] = loss;
        }

        __syncthreads();              // everyone done reading buffer (s&1)
        if (s + 2 < TPB) issue_tile(s + 2);
    }
}

extern "C" void kernel_launch(void* const* d_in, const int* in_sizes, int n_in,
                              void* d_out, int out_size)
{
    const float* pred   = (const float*)d_in[0];
    const float* target = (const float*)d_in[1];
    // d_in[2] (weight) is unused by the reference computation (LOSS_WEIGHT=1).
    float* out = (float*)d_out;

    const int n = out_size;                      // N boxes; output is [N,1] floats
    const int boxesPerBlock = BLK * TPB;         // 1280
    const int grid = (n + boxesPerBlock - 1) / boxesPerBlock;   // 3125 for N=4M
    gd_loss_kernel<<<grid, BLK>>>(pred, target, out, n);
}

// round 6
// speedup vs baseline: 1.2464x; 1.0077x over previous
#include <cuda_runtime.h>
#include <cuda_bf16.h>
#include <cstdint>

// GDLoss: elementwise Gaussian KL loss over [N,5] xywhr boxes. 176MB traffic.
// R6: persistent grid-stride blocks + 3-stage cp.async ring buffer with a
// single __syncthreads per tile. R5 showed the pipeline works (DRAM 52->72%);
// this removes the per-block fill/drain overhead (5-tile blocks spent 40% of
// tiles draining) and halves barrier count.

#define TAU_F   1.0f
#define EPS_F   1e-6f
#define BLK     256
#define STAGES  3
#define TILE_F  (BLK * 5)            // 1280 floats per tensor per tile
#define TILE_V4 (TILE_F / 4)         // 320 float4 per tensor per tile
#define GRID_P  1064                 // ~7 blocks/SM on 152-SM GB300

__device__ __forceinline__ void cp_async16(unsigned smem_dst, const void* gmem_src) {
    asm volatile("cp.async.cg.shared.global [%0], [%1], 16;\n"
                 :: "r"(smem_dst), "l"(gmem_src));
}
__device__ __forceinline__ void cp_async4(unsigned smem_dst, const void* gmem_src) {
    asm volatile("cp.async.ca.shared.global [%0], [%1], 4;\n"
                 :: "r"(smem_dst), "l"(gmem_src));
}
__device__ __forceinline__ void cp_commit() {
    asm volatile("cp.async.commit_group;\n" ::: "memory");
}
template <int N>
__device__ __forceinline__ void cp_wait() {
    asm volatile("cp.async.wait_group %0;\n" :: "n"(N) : "memory");
}

__device__ __forceinline__ float gd_loss_one(
    float px, float py, float pw, float ph, float prr,
    float tx, float ty, float tw, float th, float trr)
{
    pw = fminf(fmaxf(pw, 1e-7f), 1e7f);
    ph = fminf(fmaxf(ph, 1e-7f), 1e7f);
    tw = fminf(fmaxf(tw, 1e-7f), 1e7f);
    th = fminf(fmaxf(th, 1e-7f), 1e7f);

    float cp, spn, ct, stn;
    __sincosf(prr, &spn, &cp);
    __sincosf(trr, &stn, &ct);

    const float pa = 0.25f * pw * pw;
    const float pb = 0.25f * ph * ph;
    const float p11 = pa * cp * cp + pb * spn * spn;
    const float p12 = (pa - pb) * spn * cp;
    const float p22 = pa * spn * spn + pb * cp * cp;

    const float ta = 0.25f * tw * tw;
    const float tb = 0.25f * th * th;
    const float t11 = ta * ct * ct + tb * stn * stn;
    const float t12 = (ta - tb) * stn * ct;
    const float t22 = ta * stn * stn + tb * ct * ct;

    const float det_p = p11 * p22 - p12 * p12;
    const float det_t = t11 * t22 - t12 * t12;

    const float dx = px - tx;
    const float dy = py - ty;

    const float inv_det_t = __frcp_rn(det_t);

    const float term1 = (t22 * dx * dx - 2.0f * t12 * dx * dy + t11 * dy * dy) * inv_det_t;
    const float trace_term = (t22 * p11 - 2.0f * t12 * p12 + t11 * p22) * inv_det_t;
    const float term2 = trace_term + __logf(det_t * __frcp_rn(det_p));

    float dis = term1 + term2 - 2.0f;
    float kl = fmaxf(dis, EPS_F);
    return 1.0f - __frcp_rn(TAU_F + sqrtf(kl));
}

__global__ void __launch_bounds__(BLK) gd_loss_kernel(
    const float* __restrict__ pred,
    const float* __restrict__ target,
    float* __restrict__ out,
    int n)
{
    __shared__ float sp[STAGES][TILE_F];
    __shared__ float st[STAGES][TILE_F];

    const int tid = threadIdx.x;
    const int numTiles = (n + BLK - 1) / BLK;
    const int grid = gridDim.x;

    // Issue cp.async loads for local iteration k (tile = blockIdx.x + k*grid)
    // into ring buffer slot k % STAGES. Always commits (for wait bookkeeping).
    auto issue_k = [&](int k) {
        const long long tile = (long long)blockIdx.x + (long long)k * grid;
        if (tile < numTiles) {
            const long long tileBase = tile * BLK;
            long long nb = (long long)n - tileBase;
            if (nb > BLK) nb = BLK;
            float* spb = sp[k % STAGES];
            float* stb = st[k % STAGES];
            const float* pbase = pred   + tileBase * 5;
            const float* tbase = target + tileBase * 5;
            if (nb == BLK) {
                const float4* p4 = (const float4*)pbase;
                const float4* t4 = (const float4*)tbase;
                #pragma unroll
                for (int j = 0; j < 2; ++j) {
                    const int i = tid + j * BLK;
                    if (i < TILE_V4) {
                        cp_async16((unsigned)__cvta_generic_to_shared(((float4*)spb) + i), p4 + i);
                        cp_async16((unsigned)__cvta_generic_to_shared(((float4*)stb) + i), t4 + i);
                    }
                }
            } else {
                const int nfloats = (int)nb * 5;
                for (int i = tid; i < nfloats; i += BLK) {
                    cp_async4((unsigned)__cvta_generic_to_shared(spb + i), pbase + i);
                    cp_async4((unsigned)__cvta_generic_to_shared(stb + i), tbase + i);
                }
            }
        }
        cp_commit();
    };

    // Prologue: two tiles in flight.
    issue_k(0);
    issue_k(1);

    for (int k = 0; ; ++k) {
        const long long tile = (long long)blockIdx.x + (long long)k * grid;
        if (tile >= numTiles) break;

        cp_wait<1>();        // tile k's data landed (k+1 still in flight)
        __syncthreads();     // all threads done with compute(k-1) -> buf(k-1) free
        issue_k(k + 2);      // writes buf((k+2)%3) == buf((k-1)%3): safe

        const long long tileBase = tile * BLK;
        long long nbll = (long long)n - tileBase;
        const int nb = (nbll >= BLK) ? BLK : (int)nbll;

        if (tid < nb) {
            const float* spb = sp[k % STAGES];
            const float* stb = st[k % STAGES];
            const int b5 = tid * 5;   // stride-5 smem: gcd(5,32)=1, conflict-free
            const float loss = gd_loss_one(
                spb[b5 + 0], spb[b5 + 1], spb[b5 + 2], spb[b5 + 3], spb[b5 + 4],
                stb[b5 + 0], stb[b5 + 1], stb[b5 + 2], stb[b5 + 3], stb[b5 + 4]);
            out[tileBase + tid] = loss;
        }
    }
}

extern "C" void kernel_launch(void* const* d_in, const int* in_sizes, int n_in,
                              void* d_out, int out_size)
{
    const float* pred   = (const float*)d_in[0];
    const float* target = (const float*)d_in[1];
    // d_in[2] (weight) is unused by the reference computation (LOSS_WEIGHT=1).
    float* out = (float*)d_out;

    const int n = out_size;                      // N boxes; output is [N,1] floats
    const int numTiles = (n + BLK - 1) / BLK;    // 15625 for N=4M
    int grid = GRID_P;
    if (grid > numTiles) grid = numTiles;
    gd_loss_kernel<<<grid, BLK>>>(pred, target, out, n);
}